// round 12
// baseline (speedup 1.0000x reference)
#include <cuda_runtime.h>
#include <cstdint>

#define BB 512
#define TT 1024
#define ORDER 128
#define HH 1024
#define CC 10
#define NROWS (BB*TT)   // 524288

// ---- device scratch (module-load, not runtime allocs) ----
__device__ unsigned g_se_bits[(size_t)NROWS * 8];    // 16 MB encoder spikes
__device__ unsigned g_sh_bits[(size_t)NROWS * 32];   // 64 MB hidden spikes
__device__ float    g_I2[(size_t)NROWS * CC];        // 21 MB output currents
__device__ unsigned g_Bq1[64 * HH];                  // hidden W plane0 [kq][h]
__device__ unsigned g_Bq1t[2 * HH * 64];             // hidden W planes1,2 [p][h][kq]
__device__ unsigned g_Bq2[3 * 256 * 16];             // output W digits [p][kq][n]
__device__ float    g_cmb1[HH], g_qf1[HH];
__device__ float    g_cmb2[16], g_qf2[16];

__device__ __forceinline__ unsigned smaddr(const void* p) {
    return (unsigned)__cvta_generic_to_shared(p);
}
__device__ __forceinline__ unsigned lds32(unsigned a) {
    unsigned v; asm volatile("ld.shared.b32 %0, [%1];" : "=r"(v) : "r"(a)); return v;
}
__device__ __forceinline__ void ldmx4(unsigned a[4], unsigned addr) {
    asm volatile("ldmatrix.sync.aligned.m8n8.x4.shared.b16 {%0,%1,%2,%3}, [%4];"
                 : "=r"(a[0]), "=r"(a[1]), "=r"(a[2]), "=r"(a[3]) : "r"(addr));
}
__device__ __forceinline__ void imma16832(int c[4], const unsigned a[4],
                                          unsigned b0, unsigned b1) {
    asm volatile(
        "mma.sync.aligned.m16n8k32.row.col.s32.s8.s8.s32 "
        "{%0,%1,%2,%3}, {%4,%5,%6,%7}, {%8,%9}, {%0,%1,%2,%3};"
        : "+r"(c[0]), "+r"(c[1]), "+r"(c[2]), "+r"(c[3])
        : "r"(a[0]), "r"(a[1]), "r"(a[2]), "r"(a[3]), "r"(b0), "r"(b1));
}
// 4 spike bits -> 4 s8 bytes {0,1}: 3 ops
#define EXP4(x) ((((x) & 0xFu) * 0x00204081u) & 0x01010101u)
__device__ __forceinline__ void bar_sync(int id, int cnt) {
    asm volatile("bar.sync %0, %1;" :: "r"(id), "r"(cnt) : "memory");
}
__device__ __forceinline__ void bar_arrive(int id, int cnt) {
    asm volatile("bar.arrive %0, %1;" :: "r"(id), "r"(cnt) : "memory");
}

// ---------------------------------------------------------------------------
// scales + quantization (23-bit, per-column pow2 scales)
// ---------------------------------------------------------------------------
__global__ void k_scale1(const float* __restrict__ Wh) {
    int n = blockIdx.x * blockDim.x + threadIdx.x;
    float m = 0.f;
    for (int k = 0; k < 256; k++) m = fmaxf(m, fabsf(Wh[k * HH + n]));
    int e = (m > 0.f) ? (ilogbf(m) + 1) : 0;
    g_qf1[n]  = ldexpf(1.f, 22 - e);
    g_cmb1[n] = ldexpf(1.f, e - 22);
}
__global__ void k_scale2(const float* __restrict__ Wo) {
    int n = threadIdx.x;
    if (n >= 16) return;
    float m = 0.f;
    if (n < CC) for (int k = 0; k < HH; k++) m = fmaxf(m, fabsf(Wo[k * CC + n]));
    int e = (m > 0.f) ? (ilogbf(m) + 1) : 0;
    g_qf2[n]  = ldexpf(1.f, 22 - e);
    g_cmb2[n] = ldexpf(1.f, e - 22);
}

// hidden W -> 3 balanced base-256 digit planes; plane0 [kq][h],
// planes 1,2 transposed [p][h][kq] for the dp4a path.
__global__ void k_quantb(const float* __restrict__ Wh) {
    int gid = blockIdx.x * blockDim.x + threadIdx.x;  // 65536 = 64kq * 1024h
    int kq = gid >> 10, h = gid & 1023;
    float qf = g_qf1[h];
    unsigned wp[3] = {0, 0, 0};
#pragma unroll
    for (int j = 0; j < 4; j++) {
        int q = __float2int_rn(Wh[(4 * kq + j) * HH + h] * qf);
        int d0 = ((q + 128) & 255) - 128; q = (q - d0) >> 8;
        int d1 = ((q + 128) & 255) - 128; q = (q - d1) >> 8;   // |q| <= 66
        wp[0] |= ((unsigned)d0 & 255u) << (8 * j);
        wp[1] |= ((unsigned)d1 & 255u) << (8 * j);
        wp[2] |= ((unsigned)q  & 255u) << (8 * j);
    }
    g_Bq1[kq * HH + h] = wp[0];
    g_Bq1t[(size_t)h * 64 + kq] = wp[1];
    g_Bq1t[(size_t)(HH + h) * 64 + kq] = wp[2];
}

__global__ void k_quant2(const float* __restrict__ Wo) {
    int gid = blockIdx.x * blockDim.x + threadIdx.x;  // 4096 = 256kq * 16n
    int kq = gid >> 4, n = gid & 15;
    float qf = g_qf2[n];
    unsigned wp[3] = {0, 0, 0};
#pragma unroll
    for (int j = 0; j < 4; j++) {
        float w = (n < CC) ? Wo[(4 * kq + j) * CC + n] : 0.f;
        int q = __float2int_rn(w * qf);
        int d0 = ((q + 128) & 255) - 128; q = (q - d0) >> 8;
        int d1 = ((q + 128) & 255) - 128; q = (q - d1) >> 8;
        wp[0] |= ((unsigned)d0 & 255u) << (8 * j);
        wp[1] |= ((unsigned)d1 & 255u) << (8 * j);
        wp[2] |= ((unsigned)q  & 255u) << (8 * j);
    }
#pragma unroll
    for (int p = 0; p < 3; p++) g_Bq2[(p * 256 + kq) * 16 + n] = wp[p];
}

// ---------------------------------------------------------------------------
// encoder: IF neuron, soft reset; exact fp32 matching reference op order.
// ---------------------------------------------------------------------------
__global__ void __launch_bounds__(128, 8) k_encoder(const float* __restrict__ x) {
    int b = blockIdx.x, j = threadIdx.x;
    const float* xp = x + (size_t)b * TT * ORDER + j;
    unsigned* wp = g_se_bits + (size_t)b * TT * 8 + (j >> 5);
    float vp = 0.f, vn = 0.f;
#pragma unroll 4
    for (int t = 0; t < TT; t++) {
        float val = xp[(size_t)t * ORDER];
        vp = __fadd_rn(vp, fmaxf(val, 0.f));
        bool sp = (vp >= 1.0f);
        unsigned mp = __ballot_sync(0xffffffffu, sp);
        if (sp) vp = __fsub_rn(vp, 1.0f);
        vn = __fadd_rn(vn, fmaxf(-val, 0.f));
        bool sn = (vn >= 1.0f);
        unsigned mn = __ballot_sync(0xffffffffu, sn);
        if (sn) vn = __fsub_rn(vn, 1.0f);
        if ((j & 31) == 0) { wp[t * 8] = mp; wp[t * 8 + 4] = mn; }
    }
}

// ---------------------------------------------------------------------------
// fused hidden layer v8: M-tile 64, 3 CTAs/SM for stall hiding.
//   288 threads: warps 0-7 plane0 IMMA + planes1,2 dp4a (fragment-aligned,
//   register-local combine); warp 8 = LIF scan. 16 t-tiles of 64 rows.
// smem words: A s8 [0,4352) stride 68 | I0 [4352,6528) stride 34 |
//   I1 [6528,8704) | B0 [8704,11008) 64kq x 36w |
//   Bt [11008,15360) [p][col][kq] stride 68 | cmb [15360,15392)
// ---------------------------------------------------------------------------
#define SM_AW 0
#define SM_I0 4352
#define SM_I1 6528
#define SM_B0 8704
#define SM_BT 11008
#define SM_CW 15360
#define SMEM1 (15392 * 4)

__global__ void __launch_bounds__(288, 3) k_hidden() {
    extern __shared__ int sm[];
    const int tid = threadIdx.x, lane = tid & 31, warp = tid >> 5;
    const int ntile = blockIdx.x, b = blockIdx.y;

    if (tid < 256) {
        // ================= producers: 8 warps =================
        const int wm = warp & 3, wn = warp >> 2;      // 4(m16) x 2(n16)
        const int abase = wm * 16 + (lane >> 2);      // dp4a rows +{0,8}
        const int cbase = wn * 16 + (lane & 3) * 2;   // dp4a cols +{0,1,8,9}

        for (int i = tid; i < 2048; i += 256) {
            int kq = i >> 5, n = i & 31;
            sm[SM_B0 + kq * 36 + n] = (int)g_Bq1[kq * HH + ntile * 32 + n];
        }
        for (int i = tid; i < 4096; i += 256) {
            int p = i >> 11, col = (i >> 6) & 31, kq = i & 63;
            sm[SM_BT + p * 2176 + col * 68 + kq] =
                (int)g_Bq1t[(size_t)(p * HH + ntile * 32 + col) * 64 + kq];
        }
        if (tid < 32) ((float*)(sm + SM_CW))[tid] = g_cmb1[ntile * 32 + tid];
        // build A tile 0 (64 rows x 8 bit-words)
        for (int i = tid; i < 512; i += 256) {
            int r = i >> 3, g = i & 7;
            unsigned bits = g_se_bits[(size_t)(b * TT + r) * 8 + g];
            char* dst = (char*)sm + r * 272 + g * 32;
            uint4 u;
            u.x = EXP4(bits);       u.y = EXP4(bits >> 4);
            u.z = EXP4(bits >> 8);  u.w = EXP4(bits >> 12);
            *(uint4*)dst = u;
            u.x = EXP4(bits >> 16); u.y = EXP4(bits >> 20);
            u.z = EXP4(bits >> 24); u.w = EXP4(bits >> 28);
            *(uint4*)(dst + 16) = u;
        }
        bar_sync(1, 256);

        float cmbreg[4];
        {
            const float* cmb = (const float*)(sm + SM_CW);
            cmbreg[0] = cmb[cbase];     cmbreg[1] = cmb[cbase + 1];
            cmbreg[2] = cmb[cbase + 8]; cmbreg[3] = cmb[cbase + 9];
        }

        const unsigned Aaddr0 = smaddr(sm)
            + (wm * 16 + (lane & 15)) * 272 + (lane >> 4) * 16;
        const unsigned B0sm = smaddr(sm + SM_B0);
        const int rA = tid >> 3, gA = tid & 7;   // A-store: 2 slots/thread

        for (int mt = 0; mt < 16; mt++) {
            const int buf = mt & 1;
            int* Ib = sm + (buf ? SM_I1 : SM_I0);

            // prefetch next tile's spike bits (64 rows x 8 words = 512)
            unsigned pf0 = 0, pf1 = 0;
            if (mt < 15) {
                const unsigned* gp = g_se_bits
                    + (size_t)(b * TT + (mt + 1) * 64) * 8;
                pf0 = gp[tid]; pf1 = gp[tid + 256];
            }

            int accT[2][4];          // [nf][r]
            int p1[2][4], p2[2][4];  // [row][bc], bc -> cols {0,1,8,9}
#pragma unroll
            for (int nf = 0; nf < 2; nf++)
#pragma unroll
                for (int r = 0; r < 4; r++) accT[nf][r] = 0;
#pragma unroll
            for (int i = 0; i < 2; i++)
#pragma unroll
                for (int j = 0; j < 4; j++) { p1[i][j] = 0; p2[i][j] = 0; }

#pragma unroll 1
            for (int ks = 0; ks < 8; ks++) {
                // --- plane0 on tensor pipe (1 m16 frag) ---
                unsigned a[4];
                ldmx4(a, Aaddr0 + ks * 32);
                unsigned ba = B0sm
                    + ((ks * 8 + (lane & 3)) * 36 + wn * 16 + (lane >> 2)) * 4;
#pragma unroll
                for (int nf = 0; nf < 2; nf++) {
                    unsigned b0 = lds32(ba + nf * 32);
                    unsigned b1 = lds32(ba + 576 + nf * 32);   // kq+4
                    imma16832(accT[nf], a, b0, b1);
                }
                // --- planes 1,2 on fma pipe (dp4a), fragment-aligned ---
#pragma unroll
                for (int bb = 0; bb < 2; bb++) {
                    const int blk = ks * 2 + bb;
                    int4 A0 = *(const int4*)(sm + abase * 68 + blk * 4);
                    int4 A1 = *(const int4*)(sm + (abase + 8) * 68 + blk * 4);
                    const int coff[4] = {0, 1, 8, 9};
#pragma unroll
                    for (int bc = 0; bc < 4; bc++) {
                        int c = cbase + coff[bc];
                        int4 B1 = *(const int4*)(sm + SM_BT
                            + c * 68 + blk * 4);
                        int4 B2 = *(const int4*)(sm + SM_BT + 2176
                            + c * 68 + blk * 4);
                        p1[0][bc] = __dp4a(A0.x, B1.x, p1[0][bc]);
                        p1[0][bc] = __dp4a(A0.y, B1.y, p1[0][bc]);
                        p1[0][bc] = __dp4a(A0.z, B1.z, p1[0][bc]);
                        p1[0][bc] = __dp4a(A0.w, B1.w, p1[0][bc]);
                        p2[0][bc] = __dp4a(A0.x, B2.x, p2[0][bc]);
                        p2[0][bc] = __dp4a(A0.y, B2.y, p2[0][bc]);
                        p2[0][bc] = __dp4a(A0.z, B2.z, p2[0][bc]);
                        p2[0][bc] = __dp4a(A0.w, B2.w, p2[0][bc]);
                        p1[1][bc] = __dp4a(A1.x, B1.x, p1[1][bc]);
                        p1[1][bc] = __dp4a(A1.y, B1.y, p1[1][bc]);
                        p1[1][bc] = __dp4a(A1.z, B1.z, p1[1][bc]);
                        p1[1][bc] = __dp4a(A1.w, B1.w, p1[1][bc]);
                        p2[1][bc] = __dp4a(A1.x, B2.x, p2[1][bc]);
                        p2[1][bc] = __dp4a(A1.y, B2.y, p2[1][bc]);
                        p2[1][bc] = __dp4a(A1.z, B2.z, p2[1][bc]);
                        p2[1][bc] = __dp4a(A1.w, B2.w, p2[1][bc]);
                    }
                }
            }

            if (mt >= 2) bar_sync(4 + buf, 288);   // scan freed buf

            // combine (register-local, exact ints, one fp rounding) -> I
#pragma unroll
            for (int r = 0; r < 2; r++) {
                const int row = abase + r * 8;
#pragma unroll
                for (int nf = 0; nf < 2; nf++) {
                    int t0 = accT[nf][r * 2]
                        + (p1[r][nf * 2] + p2[r][nf * 2] * 256) * 256;
                    int t1 = accT[nf][r * 2 + 1]
                        + (p1[r][nf * 2 + 1] + p2[r][nf * 2 + 1] * 256) * 256;
                    float2 v;
                    v.x = (float)t0 * cmbreg[nf * 2];
                    v.y = (float)t1 * cmbreg[nf * 2 + 1];
                    *(float2*)(Ib + row * 34 + cbase + nf * 8) = v;
                }
            }
            asm volatile("membar.cta;" ::: "memory");
            bar_arrive(2 + buf, 288);   // buf full (for scan)
            if (mt < 2) bar_sync(6, 256);   // all A reads done (mt>=2: bar4+buf)

            if (mt < 15) {
                // store next A tile from prefetched regs (2 slots/thread)
                unsigned pw[2] = {pf0, pf1};
#pragma unroll
                for (int q = 0; q < 2; q++) {
                    int r = rA + q * 32, g = gA;
                    char* dst = (char*)sm + r * 272 + g * 32;
                    unsigned bq = pw[q];
                    uint4 u;
                    u.x = EXP4(bq);       u.y = EXP4(bq >> 4);
                    u.z = EXP4(bq >> 8);  u.w = EXP4(bq >> 12);
                    *(uint4*)dst = u;
                    u.x = EXP4(bq >> 16); u.y = EXP4(bq >> 20);
                    u.z = EXP4(bq >> 24); u.w = EXP4(bq >> 28);
                    *(uint4*)(dst + 16) = u;
                }
                bar_sync(1, 256);   // A(mt+1) ready
            }
        }
    } else {
        // ============ consumer: LIF scan warp ============
        const int hl = lane;           // h = ntile*32 + hl
        float v = 0.f;
        for (int mt = 0; mt < 16; mt++) {
            const int buf = mt & 1;
            bar_sync(2 + buf, 288);    // wait: buf full
            const float* Ic = (const float*)(sm + (buf ? SM_I1 : SM_I0)) + hl;
            unsigned* ow = g_sh_bits + (size_t)(b * TT + mt * 64) * 32 + ntile;
#pragma unroll 4
            for (int tl = 0; tl < 64; tl++) {
                float I = Ic[tl * 34];
                v = __fadd_rn(__fmul_rn(0.9f, v), I);
                bool s = (v >= 1.0f);
                unsigned m = __ballot_sync(0xffffffffu, s);
                if (s) v = __fsub_rn(v, 1.0f);
                if (hl == 0) ow[(size_t)tl * 32] = m;
            }
            bar_arrive(4 + buf, 288);  // signal: buf free
        }
    }
}

// ---------------------------------------------------------------------------
// GEMM2 (exact, 3 int8 limb planes): I2 = s_h @ W_otp, N padded 16.
// ---------------------------------------------------------------------------
#define SMEM2 ((18432 + 4224 + 16) * 4)
__global__ void __launch_bounds__(256, 1) k_gemm2() {
    extern __shared__ unsigned smu[];
    unsigned* smB = smu;           // 3p x 256kq x (24-stride, 16 n) words
    unsigned* smb = smu + 18432;   // 128 rows x 33 words spike bits
    float* smC = (float*)(smu + 18432 + 4224);

    const int tid = threadIdx.x, lane = tid & 31, warp = tid >> 5;
    const int mbase = blockIdx.x * 128;

    for (int i = tid; i < 12288; i += 256) {
        int p = i >> 12, kq = (i >> 4) & 255, n = i & 15;
        smB[(p * 256 + kq) * 24 + n] = g_Bq2[i];
    }
    for (int i = tid; i < 4096; i += 256)
        smb[(i >> 5) * 33 + (i & 31)] = g_sh_bits[(size_t)(mbase + (i >> 5)) * 32 + (i & 31)];
    if (tid < 16) smC[tid] = g_cmb2[tid];
    __syncthreads();

    int acc[3][2][4];
#pragma unroll
    for (int p = 0; p < 3; p++)
#pragma unroll
        for (int nf = 0; nf < 2; nf++)
#pragma unroll
            for (int r = 0; r < 4; r++) acc[p][nf][r] = 0;

    const int r0 = warp * 16 + (lane >> 2);
    const int sh = 4 * (lane & 3);
    const unsigned Bsm = smaddr(smB);

#pragma unroll 4
    for (int ks = 0; ks < 32; ks++) {
        unsigned w0 = smb[r0 * 33 + ks];
        unsigned w1 = smb[(r0 + 8) * 33 + ks];
        unsigned a[4];
        a[0] = EXP4(w0 >> sh);
        a[1] = EXP4(w1 >> sh);
        a[2] = EXP4(w0 >> (16 + sh));
        a[3] = EXP4(w1 >> (16 + sh));
#pragma unroll
        for (int p = 0; p < 3; p++) {
            unsigned ba = Bsm + ((p * 256 + ks * 8 + (lane & 3)) * 24 + (lane >> 2)) * 4;
#pragma unroll
            for (int nf = 0; nf < 2; nf++) {
                unsigned b0 = lds32(ba + nf * 32);
                unsigned b1 = lds32(ba + 384 + nf * 32);
                imma16832(acc[p][nf], a, b0, b1);
            }
        }
    }

    int row = mbase + r0;
#pragma unroll
    for (int nf = 0; nf < 2; nf++) {
        int cl = nf * 8 + (lane & 3) * 2;
        if (cl < CC) {
            float c0 = smC[cl], c1 = smC[cl + 1];
            float v0 = ((float)(acc[0][nf][0] + (acc[1][nf][0] << 8))
                + 65536.f * (float)acc[2][nf][0]) * c0;
            float v1 = ((float)(acc[0][nf][1] + (acc[1][nf][1] << 8))
                + 65536.f * (float)acc[2][nf][1]) * c1;
            float v2 = ((float)(acc[0][nf][2] + (acc[1][nf][2] << 8))
                + 65536.f * (float)acc[2][nf][2]) * c0;
            float v3 = ((float)(acc[0][nf][3] + (acc[1][nf][3] << 8))
                + 65536.f * (float)acc[2][nf][3]) * c1;
            *(float2*)(g_I2 + (size_t)row * CC + cl) = make_float2(v0, v1);
            *(float2*)(g_I2 + (size_t)(row + 8) * CC + cl) = make_float2(v2, v3);
        }
    }
}

// ---------------------------------------------------------------------------
// scan2: leaky integrator per (b,c); emits membrane potential each step.
// ---------------------------------------------------------------------------
__global__ void k_scan2(float* __restrict__ out) {
    int b = blockIdx.x, c = threadIdx.x;
    if (c >= CC) return;
    const float* p = g_I2 + (size_t)b * TT * CC + c;
    float* q = out + (size_t)b * TT * CC + c;
    float v = 0.f;
#pragma unroll 4
    for (int t = 0; t < TT; t++) {
        v = __fadd_rn(__fmul_rn(0.9f, v), p[(size_t)t * CC]);
        q[(size_t)t * CC] = v;
    }
}

// ---------------------------------------------------------------------------
extern "C" void kernel_launch(void* const* d_in, const int* in_sizes, int n_in,
                              void* d_out, int out_size) {
    const float* x  = (const float*)d_in[0];
    const float* Wh = (const float*)d_in[1];
    const float* Wo = (const float*)d_in[2];
    float* out = (float*)d_out;

    cudaFuncSetAttribute(k_hidden, cudaFuncAttributeMaxDynamicSharedMemorySize, SMEM1);
    cudaFuncSetAttribute(k_gemm2, cudaFuncAttributeMaxDynamicSharedMemorySize, SMEM2);

    k_scale1<<<4, 256>>>(Wh);
    k_quantb<<<256, 256>>>(Wh);
    k_encoder<<<BB, 128>>>(x);
    k_hidden<<<dim3(32, BB), 288, SMEM1>>>();
    k_scale2<<<1, 32>>>(Wo);
    k_quant2<<<16, 256>>>(Wo);
    k_gemm2<<<4096, 256, SMEM2>>>();
    k_scan2<<<BB, 32>>>(out);
}

// round 13
// speedup vs baseline: 1.1560x; 1.1560x over previous
#include <cuda_runtime.h>
#include <cstdint>

#define BB 512
#define TT 1024
#define ORDER 128
#define HH 1024
#define CC 10
#define NROWS (BB*TT)   // 524288

// ---- device scratch (module-load, not runtime allocs) ----
__device__ unsigned g_se_bits[(size_t)NROWS * 8];    // 16 MB encoder spikes
__device__ unsigned g_sh_bits[(size_t)NROWS * 32];   // 64 MB hidden spikes
__device__ float    g_I2[(size_t)NROWS * CC];        // 21 MB output currents
__device__ unsigned g_Bq1[2 * 64 * HH];              // hidden W planes0,1 [p][kq][h]
__device__ unsigned g_Bq1t[HH * 64];                 // hidden W plane2 [h][kq]
__device__ unsigned g_Bq2[3 * 256 * 16];             // output W digits [p][kq][n]
__device__ float    g_cmb1[HH], g_qf1[HH];
__device__ float    g_cmb2[16], g_qf2[16];

__device__ __forceinline__ unsigned smaddr(const void* p) {
    return (unsigned)__cvta_generic_to_shared(p);
}
__device__ __forceinline__ unsigned lds32(unsigned a) {
    unsigned v; asm volatile("ld.shared.b32 %0, [%1];" : "=r"(v) : "r"(a)); return v;
}
__device__ __forceinline__ void ldmx4(unsigned a[4], unsigned addr) {
    asm volatile("ldmatrix.sync.aligned.m8n8.x4.shared.b16 {%0,%1,%2,%3}, [%4];"
                 : "=r"(a[0]), "=r"(a[1]), "=r"(a[2]), "=r"(a[3]) : "r"(addr));
}
__device__ __forceinline__ void imma16832(int c[4], const unsigned a[4],
                                          unsigned b0, unsigned b1) {
    asm volatile(
        "mma.sync.aligned.m16n8k32.row.col.s32.s8.s8.s32 "
        "{%0,%1,%2,%3}, {%4,%5,%6,%7}, {%8,%9}, {%0,%1,%2,%3};"
        : "+r"(c[0]), "+r"(c[1]), "+r"(c[2]), "+r"(c[3])
        : "r"(a[0]), "r"(a[1]), "r"(a[2]), "r"(a[3]), "r"(b0), "r"(b1));
}
// 4 spike bits -> 4 s8 bytes {0,1}: 3 ops
#define EXP4(x) ((((x) & 0xFu) * 0x00204081u) & 0x01010101u)
__device__ __forceinline__ void bar_sync(int id, int cnt) {
    asm volatile("bar.sync %0, %1;" :: "r"(id), "r"(cnt) : "memory");
}
__device__ __forceinline__ void bar_arrive(int id, int cnt) {
    asm volatile("bar.arrive %0, %1;" :: "r"(id), "r"(cnt) : "memory");
}

// ---------------------------------------------------------------------------
// scales + quantization (23-bit, per-column pow2 scales)
// ---------------------------------------------------------------------------
__global__ void k_scale1(const float* __restrict__ Wh) {
    int n = blockIdx.x * blockDim.x + threadIdx.x;
    float m = 0.f;
    for (int k = 0; k < 256; k++) m = fmaxf(m, fabsf(Wh[k * HH + n]));
    int e = (m > 0.f) ? (ilogbf(m) + 1) : 0;
    g_qf1[n]  = ldexpf(1.f, 22 - e);
    g_cmb1[n] = ldexpf(1.f, e - 22);
}
__global__ void k_scale2(const float* __restrict__ Wo) {
    int n = threadIdx.x;
    if (n >= 16) return;
    float m = 0.f;
    if (n < CC) for (int k = 0; k < HH; k++) m = fmaxf(m, fabsf(Wo[k * CC + n]));
    int e = (m > 0.f) ? (ilogbf(m) + 1) : 0;
    g_qf2[n]  = ldexpf(1.f, 22 - e);
    g_cmb2[n] = ldexpf(1.f, e - 22);
}

// hidden W -> 3 balanced base-256 digit planes; planes 0,1 [p][kq][h] frag
// layout (tensor path), plane 2 transposed [h][kq] (dp4a path).
__global__ void k_quantb(const float* __restrict__ Wh) {
    int gid = blockIdx.x * blockDim.x + threadIdx.x;  // 65536 = 64kq * 1024h
    int kq = gid >> 10, h = gid & 1023;
    float qf = g_qf1[h];
    unsigned wp[3] = {0, 0, 0};
#pragma unroll
    for (int j = 0; j < 4; j++) {
        int q = __float2int_rn(Wh[(4 * kq + j) * HH + h] * qf);
        int d0 = ((q + 128) & 255) - 128; q = (q - d0) >> 8;
        int d1 = ((q + 128) & 255) - 128; q = (q - d1) >> 8;   // |q| <= 66
        wp[0] |= ((unsigned)d0 & 255u) << (8 * j);
        wp[1] |= ((unsigned)d1 & 255u) << (8 * j);
        wp[2] |= ((unsigned)q  & 255u) << (8 * j);
    }
    g_Bq1[kq * HH + h] = wp[0];
    g_Bq1[(64 + kq) * HH + h] = wp[1];
    g_Bq1t[(size_t)h * 64 + kq] = wp[2];
}

__global__ void k_quant2(const float* __restrict__ Wo) {
    int gid = blockIdx.x * blockDim.x + threadIdx.x;  // 4096 = 256kq * 16n
    int kq = gid >> 4, n = gid & 15;
    float qf = g_qf2[n];
    unsigned wp[3] = {0, 0, 0};
#pragma unroll
    for (int j = 0; j < 4; j++) {
        float w = (n < CC) ? Wo[(4 * kq + j) * CC + n] : 0.f;
        int q = __float2int_rn(w * qf);
        int d0 = ((q + 128) & 255) - 128; q = (q - d0) >> 8;
        int d1 = ((q + 128) & 255) - 128; q = (q - d1) >> 8;
        wp[0] |= ((unsigned)d0 & 255u) << (8 * j);
        wp[1] |= ((unsigned)d1 & 255u) << (8 * j);
        wp[2] |= ((unsigned)q  & 255u) << (8 * j);
    }
#pragma unroll
    for (int p = 0; p < 3; p++) g_Bq2[(p * 256 + kq) * 16 + n] = wp[p];
}

// ---------------------------------------------------------------------------
// encoder: IF neuron, soft reset; exact fp32 matching reference op order.
// ---------------------------------------------------------------------------
__global__ void __launch_bounds__(128, 8) k_encoder(const float* __restrict__ x) {
    int b = blockIdx.x, j = threadIdx.x;
    const float* xp = x + (size_t)b * TT * ORDER + j;
    unsigned* wp = g_se_bits + (size_t)b * TT * 8 + (j >> 5);
    float vp = 0.f, vn = 0.f;
#pragma unroll 4
    for (int t = 0; t < TT; t++) {
        float val = xp[(size_t)t * ORDER];
        vp = __fadd_rn(vp, fmaxf(val, 0.f));
        bool sp = (vp >= 1.0f);
        unsigned mp = __ballot_sync(0xffffffffu, sp);
        if (sp) vp = __fsub_rn(vp, 1.0f);
        vn = __fadd_rn(vn, fmaxf(-val, 0.f));
        bool sn = (vn >= 1.0f);
        unsigned mn = __ballot_sync(0xffffffffu, sn);
        if (sn) vn = __fsub_rn(vn, 1.0f);
        if ((j & 31) == 0) { wp[t * 8] = mp; wp[t * 8 + 4] = mn; }
    }
}

// ---------------------------------------------------------------------------
// fused hidden layer v9: planes 0,1 on tensor (IMMA), plane 2 on dp4a.
//   288 threads: warps 0-7 GEMM producers (register-local combine);
//   warp 8 = LIF scan consumer. M-tile 128, 2 CTAs/SM (R10 skeleton).
// smem words: A s8 [0,8704) stride 68 | I0 [8704,13312) stride 36 |
//   I1 [13312,17920) | B0 [17920,23040) 2p x 64kq x 40w |
//   Bt [23040,25216) 32col x 68w | cmb [25216,25248)
// ---------------------------------------------------------------------------
#define SM_AW 0
#define SM_I0 8704
#define SM_I1 13312
#define SM_B0 17920
#define SM_BT 23040
#define SM_CW 25216
#define SMEM1 (25248 * 4)

__device__ __forceinline__ void build_A(int* sm, int b, int tbase,
                                        int tid0, int nthr) {
    for (int i = tid0; i < 1024; i += nthr) {
        int r = i >> 3, g = i & 7;
        unsigned bits = g_se_bits[(size_t)(b * TT + tbase + r) * 8 + g];
        char* dst = (char*)(sm + SM_AW) + r * 272 + g * 32;
        uint4 u;
        u.x = EXP4(bits);       u.y = EXP4(bits >> 4);
        u.z = EXP4(bits >> 8);  u.w = EXP4(bits >> 12);
        *(uint4*)dst = u;
        u.x = EXP4(bits >> 16); u.y = EXP4(bits >> 20);
        u.z = EXP4(bits >> 24); u.w = EXP4(bits >> 28);
        *(uint4*)(dst + 16) = u;
    }
}

__global__ void __launch_bounds__(288, 2) k_hidden() {
    extern __shared__ int sm[];
    const int tid = threadIdx.x, lane = tid & 31, warp = tid >> 5;
    const int ntile = blockIdx.x, b = blockIdx.y;

    if (tid < 256) {
        // ================= producers: 8 warps =================
        const int wm = warp & 3, wn = warp >> 2;      // 4 x 2 warp grid
        const int abase = wm * 32 + (lane >> 2);      // dp4a rows +{0,8,16,24}
        const int cbase = wn * 16 + (lane & 3) * 2;   // dp4a cols +{0,1,8,9}

        // B planes 0,1 in frag layout; plane 2 transposed
        for (int i = tid; i < 4096; i += 256) {
            int p = i >> 11, kq = (i >> 5) & 63, n = i & 31;
            sm[SM_B0 + p * 2560 + kq * 40 + n] =
                (int)g_Bq1[(p * 64 + kq) * HH + ntile * 32 + n];
        }
        for (int i = tid; i < 2048; i += 256) {
            int col = i >> 6, kq = i & 63;
            sm[SM_BT + col * 68 + kq] =
                (int)g_Bq1t[(size_t)(ntile * 32 + col) * 64 + kq];
        }
        if (tid < 32) ((float*)(sm + SM_CW))[tid] = g_cmb1[ntile * 32 + tid];
        build_A(sm, b, 0, tid, 256);
        bar_sync(1, 256);

        float cmbreg[4];
        {
            const float* cmb = (const float*)(sm + SM_CW);
            cmbreg[0] = cmb[cbase];     cmbreg[1] = cmb[cbase + 1];
            cmbreg[2] = cmb[cbase + 8]; cmbreg[3] = cmb[cbase + 9];
        }

        const unsigned Aaddr0 = smaddr(sm + SM_AW)
            + (wm * 32 + (lane & 7) + ((lane >> 3) & 1) * 8) * 272
            + (lane >> 4) * 16;
        const unsigned B0sm = smaddr(sm + SM_B0);
        const int rA = tid >> 3, gA = tid & 7;   // A-store ownership

        for (int mt = 0; mt < 8; mt++) {
            const int buf = mt & 1;
            int* Ib = sm + (buf ? SM_I1 : SM_I0);

            // prefetch next tile's spike bits into regs (hides LDG latency)
            unsigned pf0 = 0, pf1 = 0, pf2 = 0, pf3 = 0;
            if (mt < 7) {
                const unsigned* gp = g_se_bits
                    + (size_t)(b * TT + (mt + 1) * 128) * 8;
                pf0 = gp[tid]; pf1 = gp[tid + 256];
                pf2 = gp[tid + 512]; pf3 = gp[tid + 768];
            }

            int accT[2][2][2][4];    // [plane][mf][nf][r]
            int p2[4][4];            // dp4a plane2 [ar][bc]
#pragma unroll
            for (int p = 0; p < 2; p++)
#pragma unroll
                for (int mf = 0; mf < 2; mf++)
#pragma unroll
                    for (int nf = 0; nf < 2; nf++)
#pragma unroll
                        for (int r = 0; r < 4; r++) accT[p][mf][nf][r] = 0;
#pragma unroll
            for (int i = 0; i < 4; i++)
#pragma unroll
                for (int j = 0; j < 4; j++) p2[i][j] = 0;

#pragma unroll 1
            for (int ks = 0; ks < 8; ks++) {
                // --- planes 0,1 on tensor pipe ---
                unsigned a0[4], a1[4];
                ldmx4(a0, Aaddr0 + ks * 32);
                ldmx4(a1, Aaddr0 + 16 * 272 + ks * 32);
                unsigned ba = B0sm
                    + ((ks * 8 + (lane & 3)) * 40 + wn * 16 + (lane >> 2)) * 4;
#pragma unroll
                for (int p = 0; p < 2; p++) {
                    unsigned bp = ba + p * 10240;   // plane stride 2560 words
#pragma unroll
                    for (int nf = 0; nf < 2; nf++) {
                        unsigned b0 = lds32(bp + nf * 32);
                        unsigned b1 = lds32(bp + 640 + nf * 32);   // kq+4
                        imma16832(accT[p][0][nf], a0, b0, b1);
                        imma16832(accT[p][1][nf], a1, b0, b1);
                    }
                }
                // --- plane 2 on fma pipe (dp4a), fragment-aligned ---
#pragma unroll
                for (int bb = 0; bb < 2; bb++) {
                    const int blk = ks * 2 + bb;
                    int4 Aw[4];
#pragma unroll
                    for (int ar = 0; ar < 4; ar++)
                        Aw[ar] = *(const int4*)(sm + SM_AW
                            + (abase + ar * 8) * 68 + blk * 4);
                    const int coff[4] = {0, 1, 8, 9};
#pragma unroll
                    for (int bc = 0; bc < 4; bc++) {
                        int c = cbase + coff[bc];
                        int4 B2 = *(const int4*)(sm + SM_BT
                            + c * 68 + blk * 4);
#pragma unroll
                        for (int ar = 0; ar < 4; ar++) {
                            p2[ar][bc] = __dp4a(Aw[ar].x, B2.x, p2[ar][bc]);
                            p2[ar][bc] = __dp4a(Aw[ar].y, B2.y, p2[ar][bc]);
                            p2[ar][bc] = __dp4a(Aw[ar].z, B2.z, p2[ar][bc]);
                            p2[ar][bc] = __dp4a(Aw[ar].w, B2.w, p2[ar][bc]);
                        }
                    }
                }
            }

            if (mt >= 2) bar_sync(4 + buf, 288);   // scan freed buf

            // combine: I = p0 + 256*(p1 + 256*p2) exact ints, one rounding
#pragma unroll
            for (int ar = 0; ar < 4; ar++) {
                const int row = abase + ar * 8;
                const int mf = ar >> 1;
                const int rr = (ar & 1) * 2;
#pragma unroll
                for (int nf = 0; nf < 2; nf++) {
                    int t0 = accT[0][mf][nf][rr]
                        + (accT[1][mf][nf][rr] + p2[ar][nf * 2] * 256) * 256;
                    int t1 = accT[0][mf][nf][rr + 1]
                        + (accT[1][mf][nf][rr + 1] + p2[ar][nf * 2 + 1] * 256) * 256;
                    float2 v;
                    v.x = (float)t0 * cmbreg[nf * 2];
                    v.y = (float)t1 * cmbreg[nf * 2 + 1];
                    *(float2*)(Ib + row * 36 + cbase + nf * 8) = v;
                }
            }
            asm volatile("membar.cta;" ::: "memory");
            bar_arrive(2 + buf, 288);   // buf full (for scan)
            if (mt < 2) bar_sync(6, 256);   // all A reads done (mt>=2: bar4+buf)

            if (mt < 7) {
                // store next A tile from prefetched regs
                char* dst = (char*)sm + rA * 272 + gA * 32;
                unsigned pw[4] = {pf0, pf1, pf2, pf3};
#pragma unroll
                for (int q = 0; q < 4; q++) {
                    unsigned bq = pw[q];
                    uint4 u;
                    u.x = EXP4(bq);       u.y = EXP4(bq >> 4);
                    u.z = EXP4(bq >> 8);  u.w = EXP4(bq >> 12);
                    *(uint4*)(dst + q * 8704) = u;
                    u.x = EXP4(bq >> 16); u.y = EXP4(bq >> 20);
                    u.z = EXP4(bq >> 24); u.w = EXP4(bq >> 28);
                    *(uint4*)(dst + q * 8704 + 16) = u;
                }
                bar_sync(1, 256);   // A(mt+1) ready
            }
        }
    } else {
        // ============ consumer: LIF scan warp ============
        const int hl = lane;           // h = ntile*32 + hl
        float v = 0.f;
        for (int mt = 0; mt < 8; mt++) {
            const int buf = mt & 1;
            bar_sync(2 + buf, 288);    // wait: buf full
            const float* Ic = (const float*)(sm + (buf ? SM_I1 : SM_I0)) + hl;
            unsigned* ow = g_sh_bits + (size_t)(b * TT + mt * 128) * 32 + ntile;
#pragma unroll 4
            for (int tl = 0; tl < 128; tl++) {
                float I = Ic[tl * 36];
                v = __fadd_rn(__fmul_rn(0.9f, v), I);
                bool s = (v >= 1.0f);
                unsigned m = __ballot_sync(0xffffffffu, s);
                if (s) v = __fsub_rn(v, 1.0f);
                if (hl == 0) ow[(size_t)tl * 32] = m;
            }
            bar_arrive(4 + buf, 288);  // signal: buf free
        }
    }
}

// ---------------------------------------------------------------------------
// GEMM2 (exact, 3 int8 limb planes): I2 = s_h @ W_otp, N padded 16.
// ---------------------------------------------------------------------------
#define SMEM2 ((18432 + 4224 + 16) * 4)
__global__ void __launch_bounds__(256, 1) k_gemm2() {
    extern __shared__ unsigned smu[];
    unsigned* smB = smu;           // 3p x 256kq x (24-stride, 16 n) words
    unsigned* smb = smu + 18432;   // 128 rows x 33 words spike bits
    float* smC = (float*)(smu + 18432 + 4224);

    const int tid = threadIdx.x, lane = tid & 31, warp = tid >> 5;
    const int mbase = blockIdx.x * 128;

    for (int i = tid; i < 12288; i += 256) {
        int p = i >> 12, kq = (i >> 4) & 255, n = i & 15;
        smB[(p * 256 + kq) * 24 + n] = g_Bq2[i];
    }
    for (int i = tid; i < 4096; i += 256)
        smb[(i >> 5) * 33 + (i & 31)] = g_sh_bits[(size_t)(mbase + (i >> 5)) * 32 + (i & 31)];
    if (tid < 16) smC[tid] = g_cmb2[tid];
    __syncthreads();

    int acc[3][2][4];
#pragma unroll
    for (int p = 0; p < 3; p++)
#pragma unroll
        for (int nf = 0; nf < 2; nf++)
#pragma unroll
            for (int r = 0; r < 4; r++) acc[p][nf][r] = 0;

    const int r0 = warp * 16 + (lane >> 2);
    const int sh = 4 * (lane & 3);
    const unsigned Bsm = smaddr(smB);

#pragma unroll 4
    for (int ks = 0; ks < 32; ks++) {
        unsigned w0 = smb[r0 * 33 + ks];
        unsigned w1 = smb[(r0 + 8) * 33 + ks];
        unsigned a[4];
        a[0] = EXP4(w0 >> sh);
        a[1] = EXP4(w1 >> sh);
        a[2] = EXP4(w0 >> (16 + sh));
        a[3] = EXP4(w1 >> (16 + sh));
#pragma unroll
        for (int p = 0; p < 3; p++) {
            unsigned ba = Bsm + ((p * 256 + ks * 8 + (lane & 3)) * 24 + (lane >> 2)) * 4;
#pragma unroll
            for (int nf = 0; nf < 2; nf++) {
                unsigned b0 = lds32(ba + nf * 32);
                unsigned b1 = lds32(ba + 384 + nf * 32);
                imma16832(acc[p][nf], a, b0, b1);
            }
        }
    }

    int row = mbase + r0;
#pragma unroll
    for (int nf = 0; nf < 2; nf++) {
        int cl = nf * 8 + (lane & 3) * 2;
        if (cl < CC) {
            float c0 = smC[cl], c1 = smC[cl + 1];
            float v0 = ((float)(acc[0][nf][0] + (acc[1][nf][0] << 8))
                + 65536.f * (float)acc[2][nf][0]) * c0;
            float v1 = ((float)(acc[0][nf][1] + (acc[1][nf][1] << 8))
                + 65536.f * (float)acc[2][nf][1]) * c1;
            float v2 = ((float)(acc[0][nf][2] + (acc[1][nf][2] << 8))
                + 65536.f * (float)acc[2][nf][2]) * c0;
            float v3 = ((float)(acc[0][nf][3] + (acc[1][nf][3] << 8))
                + 65536.f * (float)acc[2][nf][3]) * c1;
            *(float2*)(g_I2 + (size_t)row * CC + cl) = make_float2(v0, v1);
            *(float2*)(g_I2 + (size_t)(row + 8) * CC + cl) = make_float2(v2, v3);
        }
    }
}

// ---------------------------------------------------------------------------
// scan2: leaky integrator per (b,c); emits membrane potential each step.
// ---------------------------------------------------------------------------
__global__ void k_scan2(float* __restrict__ out) {
    int b = blockIdx.x, c = threadIdx.x;
    if (c >= CC) return;
    const float* p = g_I2 + (size_t)b * TT * CC + c;
    float* q = out + (size_t)b * TT * CC + c;
    float v = 0.f;
#pragma unroll 4
    for (int t = 0; t < TT; t++) {
        v = __fadd_rn(__fmul_rn(0.9f, v), p[(size_t)t * CC]);
        q[(size_t)t * CC] = v;
    }
}

// ---------------------------------------------------------------------------
extern "C" void kernel_launch(void* const* d_in, const int* in_sizes, int n_in,
                              void* d_out, int out_size) {
    const float* x  = (const float*)d_in[0];
    const float* Wh = (const float*)d_in[1];
    const float* Wo = (const float*)d_in[2];
    float* out = (float*)d_out;

    cudaFuncSetAttribute(k_hidden, cudaFuncAttributeMaxDynamicSharedMemorySize, SMEM1);
    cudaFuncSetAttribute(k_gemm2, cudaFuncAttributeMaxDynamicSharedMemorySize, SMEM2);

    k_scale1<<<4, 256>>>(Wh);
    k_quantb<<<256, 256>>>(Wh);
    k_encoder<<<BB, 128>>>(x);
    k_hidden<<<dim3(32, BB), 288, SMEM1>>>();
    k_scale2<<<1, 32>>>(Wo);
    k_quant2<<<16, 256>>>(Wo);
    k_gemm2<<<4096, 256, SMEM2>>>();
    k_scan2<<<BB, 32>>>(out);
}